// round 12
// baseline (speedup 1.0000x reference)
#include <cuda_runtime.h>
#include <cuda_fp16.h>
#include <cstdint>

// ---------------- problem constants ----------------
#define B_   64
#define N_   10000
#define D_   66
#define E_   160000
#define O_   64
#define RH   4224            // halves per x row = 64*66 (unpadded)
#define RU4  528             // uint4 per x row
#define ROWB 8448            // bytes per x row
#define KPAD 384             // W'^T logical row length (k=m*72+d, zeros padded)
#define KS   392             // smem-padded W'^T row (bank-conflict-free)
#define NPAIR 5000
#define GEMM_GRID 296

// ---------------- scratch (slack for GEMM tail overreads) ----------------
__device__ __half g_x0h [42241024];
__device__ __half g_x1a [42241024];
__device__ __half g_ya  [42241024];
__device__ __half g_x1b [42241024];
__device__ __half g_yb  [42241024];
__device__ __half g_wt  [64 * KPAD];   // W'^T fp16, [o][k=m*72+d], zeros padded

__device__ int   g_cnt [2][N_];        // zero-on-entry invariant (re-zeroed by GEMM)
__device__ int   g_rp  [2][N_ + 1];
__device__ int   g_cur [2][N_];
__device__ int2  g_cvS [2][E_];        // (col byte-offset, val as fp16 bits)

// ---------------- kernels ----------------

// launch 1: histogram both supports (cnt must be zero on entry; invariant)
__global__ void k_hist2(const int* __restrict__ rows0, const int* __restrict__ rows1,
                        int* __restrict__ cnt) {
    int e = blockIdx.x * blockDim.x + threadIdx.x;
    if (e < E_) atomicAdd(&cnt[rows0[e]], 1);
    else if (e < 2 * E_) atomicAdd(&cnt[N_ + rows1[e - E_]], 1);
}

// launch 2: grid = 2 blocks, one per support
__global__ void k_scan(const int* __restrict__ cnt_all, int* __restrict__ rp_all,
                       int* __restrict__ cur_all) {
    __shared__ int part[1024];
    const int CH = 10;
    const int s = blockIdx.x;
    const int* cnt = cnt_all + s * N_;
    int* rowptr = rp_all + s * (N_ + 1);
    int* cursor = cur_all + s * N_;
    int t = threadIdx.x;
    int base = t * CH;
    int loc[CH];
    int acc = 0;
#pragma unroll
    for (int j = 0; j < CH; j++) {
        int i = base + j;
        int c = (i < N_) ? cnt[i] : 0;
        loc[j] = c;
        acc += c;
    }
    part[t] = acc;
    __syncthreads();
    for (int off = 1; off < 1024; off <<= 1) {
        int v = (t >= off) ? part[t - off] : 0;
        __syncthreads();
        part[t] += v;
        __syncthreads();
    }
    int off0 = (t > 0) ? part[t - 1] : 0;
#pragma unroll
    for (int j = 0; j < CH; j++) {
        int i = base + j;
        if (i < N_) {
            rowptr[i] = off0;
            cursor[i] = off0;
            off0 += loc[j];
        }
    }
    if (t == 1023) rowptr[N_] = part[1023];
}

// launch 3: fused scatter (blocks 0..1249) + transpose (blocks 1250..11249)
//           + W' build (blocks 11250..)
__global__ void __launch_bounds__(256) k_fuse(
    const int* __restrict__ rows0, const int* __restrict__ cols0,
    const float* __restrict__ vals0,
    const int* __restrict__ rows1, const int* __restrict__ cols1,
    const float* __restrict__ vals1,
    int* __restrict__ cur_all, int2* __restrict__ cvS_all,
    const float* __restrict__ in, half2* __restrict__ x0h,
    const float* __restrict__ w, __half* __restrict__ wt) {
    int bx = blockIdx.x;
    if (bx < 1250) {
        int e = bx * 256 + threadIdx.x;
        if (e < E_) {
            int r = rows0[e];
            int p = atomicAdd(&cur_all[r], 1);
            __half h = __float2half_rn(vals0[e]);
            cvS_all[p] = make_int2(cols0[e] * ROWB,
                                   (int)*reinterpret_cast<unsigned short*>(&h));
        } else if (e < 2 * E_) {
            int ee = e - E_;
            int r = rows1[ee];
            int p = atomicAdd(&cur_all[N_ + r], 1);
            __half h = __float2half_rn(vals1[ee]);
            cvS_all[E_ + p] = make_int2(cols1[ee] * ROWB,
                                        (int)*reinterpret_cast<unsigned short*>(&h));
        }
    } else if (bx < 11250) {
        int n = bx - 1250;
        for (int j = threadIdx.x; j < RH / 2; j += 256) {
            int i = 2 * j;
            int b = i / D_, d = i - b * D_;
            float2 v = *reinterpret_cast<const float2*>(in + (size_t)b * (N_ * D_) +
                                                        (size_t)n * D_ + d);
            x0h[(size_t)n * (RH / 2) + j] = __floats2half2_rn(v.x, v.y);
        }
    } else {
        int i = (bx - 11250) * 256 + threadIdx.x;
        if (i < 64 * KPAD) {
            int o = i / KPAD, k = i - o * KPAD;
            int m = k / 72, d = k - m * 72;
            float v = 0.f;
            if (m < 5 && d < D_) {
                if (m == 0)
                    v = w[(d * 5 + 0) * 64 + o] - w[(d * 5 + 2) * 64 + o] -
                        w[(d * 5 + 4) * 64 + o];
                else if (m == 2 || m == 4)
                    v = 2.0f * w[(d * 5 + m) * 64 + o];
                else
                    v = w[(d * 5 + m) * 64 + o];
            }
            wt[i] = __float2half_rn(v);
        }
    }
}

// launches 4-7: HMMA-based CSR SpMM.
// One block per row (544 threads = 17 full warps, 528 gather lanes of uint4).
// Per edge pair (A,B): mma m16n8k16 with block-diagonal B-fragment
//   B[k][n] = vA*(k==n) + vB*(k==n+8)
// so D[m][n] += vA*A[m][n] + vB*A[m][n+8]; the LDG.128 of 8 gathered features
// IS the A-fragment (a0=uA.x a1=uA.y a2=uB.x a3=uB.y; .z/.w in second mma).
// fp32 accumulate; only new rounding vs scalar path is v -> fp16.
__global__ void __launch_bounds__(544) k_spmm_mma(
    const int* __restrict__ rowptr, const int2* __restrict__ cvS,
    const char* __restrict__ xbase, uint4* __restrict__ yh) {
    __shared__ int2 scv[546];
    int r = blockIdx.x;
    int t = threadIdx.x;
    int lane = t & 31;
    int g = lane >> 2, t4 = lane & 3;
    bool own = ((g >> 1) == t4);
    unsigned shift = (unsigned)((g & 1) * 16);
    int i4 = min(t, RU4 - 1);
    bool act = (t < RU4);
    int e0 = __ldg(rowptr + r), e1 = __ldg(rowptr + r + 1);

    const char* xp = xbase + (size_t)i4 * 16;

    float d0 = 0.f, d1 = 0.f, d2 = 0.f, d3 = 0.f;
    float d4 = 0.f, d5 = 0.f, d6 = 0.f, d7 = 0.f;

    for (int es = e0; es < e1; es += 544) {
        if (es != e0) __syncthreads();
        int ne = min(544, e1 - es);
        if (t < ne) scv[t] = cvS[es + t];
        if ((ne & 1) && t == ne)                       // pad odd tail with v=0
            scv[t] = make_int2(cvS[es + ne - 1].x, 0);
        __syncthreads();
        int nep = (ne + 1) & ~1;
#pragma unroll 2
        for (int j = 0; j < nep; j += 2) {
            int2 cvA = scv[j];
            int2 cvB = scv[j + 1];
            uint4 uA = *reinterpret_cast<const uint4*>(xp + (unsigned)cvA.x);
            uint4 uB = *reinterpret_cast<const uint4*>(xp + (unsigned)cvB.x);
            unsigned bA = own ? ((unsigned)cvA.y << shift) : 0u;
            unsigned bB = own ? ((unsigned)cvB.y << shift) : 0u;
            asm volatile(
                "mma.sync.aligned.m16n8k16.row.col.f32.f16.f16.f32 "
                "{%0,%1,%2,%3}, {%4,%5,%6,%7}, {%8,%9}, {%0,%1,%2,%3};"
                : "+f"(d0), "+f"(d1), "+f"(d2), "+f"(d3)
                : "r"(uA.x), "r"(uA.y), "r"(uB.x), "r"(uB.y), "r"(bA), "r"(bB));
            asm volatile(
                "mma.sync.aligned.m16n8k16.row.col.f32.f16.f16.f32 "
                "{%0,%1,%2,%3}, {%4,%5,%6,%7}, {%8,%9}, {%0,%1,%2,%3};"
                : "+f"(d4), "+f"(d5), "+f"(d6), "+f"(d7)
                : "r"(uA.z), "r"(uA.w), "r"(uB.z), "r"(uB.w), "r"(bA), "r"(bB));
        }
    }
    if (act) {
        half2 h0 = __floats2half2_rn(d0, d1);
        half2 h1 = __floats2half2_rn(d2, d3);
        half2 h2 = __floats2half2_rn(d4, d5);
        half2 h3 = __floats2half2_rn(d6, d7);
        uint4 o;
        o.x = *reinterpret_cast<unsigned*>(&h0);
        o.y = *reinterpret_cast<unsigned*>(&h1);
        o.z = *reinterpret_cast<unsigned*>(&h2);
        o.w = *reinterpret_cast<unsigned*>(&h3);
        yh[(size_t)r * RU4 + i4] = o;
    }
}

// launch 8: HMMA GEMM (mma.sync m16n8k16). Also restores cnt=0 invariant.
// Logical k = m*72+d lives in B (zeros at d>=66); A is unpadded (stride 66).
__global__ void __launch_bounds__(256, 2) k_gemm_mma(
    const __half* __restrict__ x0, const __half* __restrict__ x1a,
    const __half* __restrict__ ya, const __half* __restrict__ x1b,
    const __half* __restrict__ yb, const __half* __restrict__ wt,
    const float* __restrict__ bias, float* __restrict__ out,
    int* __restrict__ cnt) {
    extern __shared__ __half sB[];   // [64][KS]
    int t = threadIdx.x, wid = t >> 5, lane = t & 31;
    int g = lane >> 2, tid4 = lane & 3;

    // restore cnt = 0 for the next call (cnt is dead after k_scan)
    int zi = blockIdx.x * 256 + t;
    if (zi < 2 * N_) cnt[zi] = 0;

    const uint4* wt4 = reinterpret_cast<const uint4*>(wt);
    for (int i = t; i < 3072; i += 256) {
        int r = i / 48, c = i - r * 48;
        *reinterpret_cast<uint4*>(sB + r * KS + c * 8) = wt4[i];
    }
    __syncthreads();

    int p = wid >> 2;               // node within pair
    int b_lo = (wid & 3) * 16 + g;  // batch row (lo); hi = +8
    const __half* xs[5] = {x0, x1a, ya, x1b, yb};

    for (int tile = blockIdx.x; tile < NPAIR; tile += gridDim.x) {
        int n = tile * 2 + p;
        size_t baseL = (size_t)n * RH + (size_t)b_lo * D_ + tid4 * 2;
        size_t baseH = baseL + 8 * D_;

        float acc[8][4];
#pragma unroll
        for (int ng = 0; ng < 8; ng++)
#pragma unroll
            for (int q = 0; q < 4; q++) acc[ng][q] = 0.f;

#pragma unroll
        for (int ks = 0; ks < 23; ks++) {
            const int klo = ks * 16;
            const int khi = klo + 8;
            const int mlo = klo / 72, dlo = klo - mlo * 72;
            const int mhi = khi / 72, dhi = khi - mhi * 72;
            unsigned a0, a1, a2, a3;
            a0 = *reinterpret_cast<const unsigned*>(xs[mlo] + baseL + dlo);
            a1 = *reinterpret_cast<const unsigned*>(xs[mlo] + baseH + dlo);
            if (mhi < 5) {
                a2 = *reinterpret_cast<const unsigned*>(xs[mhi] + baseL + dhi);
                a3 = *reinterpret_cast<const unsigned*>(xs[mhi] + baseH + dhi);
            } else {
                a2 = 0u; a3 = 0u;
            }
#pragma unroll
            for (int ng = 0; ng < 8; ng++) {
                const __half* bp = sB + (ng * 8 + g) * KS + klo + tid4 * 2;
                unsigned b0 = *reinterpret_cast<const unsigned*>(bp);
                unsigned b1 = *reinterpret_cast<const unsigned*>(bp + 8);
                asm volatile(
                    "mma.sync.aligned.m16n8k16.row.col.f32.f16.f16.f32 "
                    "{%0,%1,%2,%3}, {%4,%5,%6,%7}, {%8,%9}, {%0,%1,%2,%3};"
                    : "+f"(acc[ng][0]), "+f"(acc[ng][1]),
                      "+f"(acc[ng][2]), "+f"(acc[ng][3])
                    : "r"(a0), "r"(a1), "r"(a2), "r"(a3), "r"(b0), "r"(b1));
            }
        }

        float* orow_lo = out + (size_t)b_lo * ((size_t)N_ * O_) + (size_t)n * O_;
        float* orow_hi = orow_lo + 8 * ((size_t)N_ * O_);
#pragma unroll
        for (int ng = 0; ng < 8; ng++) {
            int col = ng * 8 + tid4 * 2;
            float2 bv = __ldg(reinterpret_cast<const float2*>(bias + col));
            float2 vlo = make_float2(acc[ng][0] + bv.x, acc[ng][1] + bv.y);
            float2 vhi = make_float2(acc[ng][2] + bv.x, acc[ng][3] + bv.y);
            *reinterpret_cast<float2*>(orow_lo + col) = vlo;
            *reinterpret_cast<float2*>(orow_hi + col) = vhi;
        }
    }
}

// ---------------- launch ----------------
extern "C" void kernel_launch(void* const* d_in, const int* in_sizes, int n_in,
                              void* d_out, int out_size) {
    const float* inputs = (const float*)d_in[0];
    const float* weight = (const float*)d_in[2];
    const float* biases = (const float*)d_in[3];
    const float* vals0  = (const float*)d_in[4];
    const float* vals1  = (const float*)d_in[5];
    const int*   rows0  = (const int*)d_in[6];
    const int*   cols0  = (const int*)d_in[7];
    const int*   rows1  = (const int*)d_in[8];
    const int*   cols1  = (const int*)d_in[9];
    float* out = (float*)d_out;

    __half *x0h, *x1a, *ya, *x1b, *yb, *wt;
    int *cnt, *rp, *cur;
    int2* cvS;
    cudaGetSymbolAddress((void**)&x0h, g_x0h);
    cudaGetSymbolAddress((void**)&x1a, g_x1a);
    cudaGetSymbolAddress((void**)&ya,  g_ya);
    cudaGetSymbolAddress((void**)&x1b, g_x1b);
    cudaGetSymbolAddress((void**)&yb,  g_yb);
    cudaGetSymbolAddress((void**)&wt,  g_wt);
    cudaGetSymbolAddress((void**)&cnt, g_cnt);
    cudaGetSymbolAddress((void**)&rp,  g_rp);
    cudaGetSymbolAddress((void**)&cur, g_cur);
    cudaGetSymbolAddress((void**)&cvS, g_cvS);

    // 1: histogram (cnt zero-on-entry invariant)
    k_hist2<<<(2 * E_ + 255) / 256, 256>>>(rows0, rows1, cnt);
    // 2: scan
    k_scan<<<2, 1024>>>(cnt, rp, cur);
    // 3: fused scatter + transpose + W' build
    k_fuse<<<11250 + (64 * KPAD + 255) / 256, 256>>>(
        rows0, cols0, vals0, rows1, cols1, vals1, cur, cvS,
        inputs, (half2*)x0h, weight, wt);

    int* rp0 = rp;
    int* rp1 = rp + (N_ + 1);
    int2* cvS0 = cvS;
    int2* cvS1 = cvS + E_;

    // 4-7: HMMA SpMM (one block per row; stage-1 pair first so x0 stays hot)
    k_spmm_mma<<<N_, 544>>>(rp0, cvS0, (const char*)x0h, (uint4*)x1a);
    k_spmm_mma<<<N_, 544>>>(rp1, cvS1, (const char*)x0h, (uint4*)x1b);
    k_spmm_mma<<<N_, 544>>>(rp0, cvS0, (const char*)x1a, (uint4*)ya);
    k_spmm_mma<<<N_, 544>>>(rp1, cvS1, (const char*)x1b, (uint4*)yb);

    // 8: GEMM (+ cnt re-zero)
    const int smem_gemm = 64 * KS * 2;  // 50176 B
    cudaFuncSetAttribute(k_gemm_mma, cudaFuncAttributeMaxDynamicSharedMemorySize, smem_gemm);
    k_gemm_mma<<<GEMM_GRID, 256, smem_gemm>>>(x0h, x1a, ya, x1b, yb, wt, biases, out, cnt);
}

// round 13
// speedup vs baseline: 1.1646x; 1.1646x over previous
#include <cuda_runtime.h>
#include <cuda_fp16.h>
#include <cstdint>

// ---------------- problem constants ----------------
#define B_   64
#define N_   10000
#define D_   66
#define E_   160000
#define O_   64
#define RH   4224            // halves per x row = 64*66 (unpadded)
#define RU4  528             // uint4 per x row
#define U4T  264             // uint4 per feature half (2 halves)
#define ROWB 8448            // bytes per x row
#define KPAD 384             // W'^T logical row length (k=m*72+d, zeros padded)
#define KS   392             // smem-padded W'^T row (bank-conflict-free)
#define NPAIR 5000
#define GEMM_GRID 296

// ---------------- scratch (slack for GEMM tail overreads) ----------------
__device__ __half g_x0h [42241024];
__device__ __half g_x1a [42241024];
__device__ __half g_ya  [42241024];
__device__ __half g_x1b [42241024];
__device__ __half g_yb  [42241024];
__device__ __half g_wt  [64 * KPAD];   // W'^T fp16, [o][k=m*72+d], zeros padded

__device__ int   g_cnt [2][N_];        // zero-on-entry invariant (re-zeroed by GEMM)
__device__ int   g_rp  [2][N_ + 1];
__device__ int   g_cur [2][N_];
__device__ int2  g_cvS [2][E_];        // (col byte-offset, val as fp16 bits)

// ---------------- kernels ----------------

// launch 1: histogram both supports (cnt must be zero on entry; invariant)
__global__ void k_hist2(const int* __restrict__ rows0, const int* __restrict__ rows1,
                        int* __restrict__ cnt) {
    int e = blockIdx.x * blockDim.x + threadIdx.x;
    if (e < E_) atomicAdd(&cnt[rows0[e]], 1);
    else if (e < 2 * E_) atomicAdd(&cnt[N_ + rows1[e - E_]], 1);
}

// launch 2: grid = 2 blocks, one per support
__global__ void k_scan(const int* __restrict__ cnt_all, int* __restrict__ rp_all,
                       int* __restrict__ cur_all) {
    __shared__ int part[1024];
    const int CH = 10;
    const int s = blockIdx.x;
    const int* cnt = cnt_all + s * N_;
    int* rowptr = rp_all + s * (N_ + 1);
    int* cursor = cur_all + s * N_;
    int t = threadIdx.x;
    int base = t * CH;
    int loc[CH];
    int acc = 0;
#pragma unroll
    for (int j = 0; j < CH; j++) {
        int i = base + j;
        int c = (i < N_) ? cnt[i] : 0;
        loc[j] = c;
        acc += c;
    }
    part[t] = acc;
    __syncthreads();
    for (int off = 1; off < 1024; off <<= 1) {
        int v = (t >= off) ? part[t - off] : 0;
        __syncthreads();
        part[t] += v;
        __syncthreads();
    }
    int off0 = (t > 0) ? part[t - 1] : 0;
#pragma unroll
    for (int j = 0; j < CH; j++) {
        int i = base + j;
        if (i < N_) {
            rowptr[i] = off0;
            cursor[i] = off0;
            off0 += loc[j];
        }
    }
    if (t == 1023) rowptr[N_] = part[1023];
}

// launch 3: fused scatter (blocks 0..1249) + transpose (blocks 1250..11249)
//           + W' build (blocks 11250..)
__global__ void __launch_bounds__(256) k_fuse(
    const int* __restrict__ rows0, const int* __restrict__ cols0,
    const float* __restrict__ vals0,
    const int* __restrict__ rows1, const int* __restrict__ cols1,
    const float* __restrict__ vals1,
    int* __restrict__ cur_all, int2* __restrict__ cvS_all,
    const float* __restrict__ in, half2* __restrict__ x0h,
    const float* __restrict__ w, __half* __restrict__ wt) {
    int bx = blockIdx.x;
    if (bx < 1250) {
        int e = bx * 256 + threadIdx.x;
        if (e < E_) {
            int r = rows0[e];
            int p = atomicAdd(&cur_all[r], 1);
            __half h = __float2half_rn(vals0[e]);
            cvS_all[p] = make_int2(cols0[e] * ROWB,
                                   (int)*reinterpret_cast<unsigned short*>(&h));
        } else if (e < 2 * E_) {
            int ee = e - E_;
            int r = rows1[ee];
            int p = atomicAdd(&cur_all[N_ + r], 1);
            __half h = __float2half_rn(vals1[ee]);
            cvS_all[E_ + p] = make_int2(cols1[ee] * ROWB,
                                        (int)*reinterpret_cast<unsigned short*>(&h));
        }
    } else if (bx < 11250) {
        int n = bx - 1250;
        for (int j = threadIdx.x; j < RH / 2; j += 256) {
            int i = 2 * j;
            int b = i / D_, d = i - b * D_;
            float2 v = *reinterpret_cast<const float2*>(in + (size_t)b * (N_ * D_) +
                                                        (size_t)n * D_ + d);
            x0h[(size_t)n * (RH / 2) + j] = __floats2half2_rn(v.x, v.y);
        }
    } else {
        int i = (bx - 11250) * 256 + threadIdx.x;
        if (i < 64 * KPAD) {
            int o = i / KPAD, k = i - o * KPAD;
            int m = k / 72, d = k - m * 72;
            float v = 0.f;
            if (m < 5 && d < D_) {
                if (m == 0)
                    v = w[(d * 5 + 0) * 64 + o] - w[(d * 5 + 2) * 64 + o] -
                        w[(d * 5 + 4) * 64 + o];
                else if (m == 2 || m == 4)
                    v = 2.0f * w[(d * 5 + m) * 64 + o];
                else
                    v = w[(d * 5 + m) * 64 + o];
            }
            wt[i] = __float2half_rn(v);
        }
    }
}

// launches 4-7: HMMA-based CSR SpMM, half-row blocking for L2 residency.
// grid (N, 2); 288 threads = 9 full warps; 264 active u4 lanes per half.
// Per edge pair (A,B): mma m16n8k16 with block-diagonal B-fragment
//   B[k][n] = vA*(k==n) + vB*(k==n+8)
// so D[m][n] += vA*A[m][n] + vB*A[m][n+8]; the LDG.128 of 8 gathered features
// IS the A-fragment (a0=uA.x a1=uA.y a2=uB.x a3=uB.y; .z/.w in second mma).
// fp32 accumulate; only new rounding vs scalar path is v -> fp16.
__global__ void __launch_bounds__(288) k_spmm_mma(
    const int* __restrict__ rowptr, const int2* __restrict__ cvS,
    const char* __restrict__ xbase, uint4* __restrict__ yh) {
    __shared__ int2 scv[290];
    int r = blockIdx.x;
    int t = threadIdx.x;
    int lane = t & 31;
    int g = lane >> 2, t4 = lane & 3;
    bool own = ((g >> 1) == t4);
    unsigned shift = (unsigned)((g & 1) * 16);
    int i4 = blockIdx.y * U4T + min(t, U4T - 1);
    bool act = (t < U4T);
    int e0 = __ldg(rowptr + r), e1 = __ldg(rowptr + r + 1);

    const char* xp = xbase + (size_t)i4 * 16;

    float d0 = 0.f, d1 = 0.f, d2 = 0.f, d3 = 0.f;
    float d4 = 0.f, d5 = 0.f, d6 = 0.f, d7 = 0.f;

    for (int es = e0; es < e1; es += 288) {
        if (es != e0) __syncthreads();
        int ne = min(288, e1 - es);
        if (t < ne) scv[t] = cvS[es + t];
        if ((ne & 1) && t == ne)                       // pad odd tail with v=0
            scv[t] = make_int2(cvS[es + ne - 1].x, 0);
        __syncthreads();
        int nep = (ne + 1) & ~1;
#pragma unroll 2
        for (int j = 0; j < nep; j += 2) {
            int2 cvA = scv[j];
            int2 cvB = scv[j + 1];
            uint4 uA = *reinterpret_cast<const uint4*>(xp + (unsigned)cvA.x);
            uint4 uB = *reinterpret_cast<const uint4*>(xp + (unsigned)cvB.x);
            unsigned bA = own ? ((unsigned)cvA.y << shift) : 0u;
            unsigned bB = own ? ((unsigned)cvB.y << shift) : 0u;
            asm volatile(
                "mma.sync.aligned.m16n8k16.row.col.f32.f16.f16.f32 "
                "{%0,%1,%2,%3}, {%4,%5,%6,%7}, {%8,%9}, {%0,%1,%2,%3};"
                : "+f"(d0), "+f"(d1), "+f"(d2), "+f"(d3)
                : "r"(uA.x), "r"(uA.y), "r"(uB.x), "r"(uB.y), "r"(bA), "r"(bB));
            asm volatile(
                "mma.sync.aligned.m16n8k16.row.col.f32.f16.f16.f32 "
                "{%0,%1,%2,%3}, {%4,%5,%6,%7}, {%8,%9}, {%0,%1,%2,%3};"
                : "+f"(d4), "+f"(d5), "+f"(d6), "+f"(d7)
                : "r"(uA.z), "r"(uA.w), "r"(uB.z), "r"(uB.w), "r"(bA), "r"(bB));
        }
    }
    if (act) {
        half2 h0 = __floats2half2_rn(d0, d1);
        half2 h1 = __floats2half2_rn(d2, d3);
        half2 h2 = __floats2half2_rn(d4, d5);
        half2 h3 = __floats2half2_rn(d6, d7);
        uint4 o;
        o.x = *reinterpret_cast<unsigned*>(&h0);
        o.y = *reinterpret_cast<unsigned*>(&h1);
        o.z = *reinterpret_cast<unsigned*>(&h2);
        o.w = *reinterpret_cast<unsigned*>(&h3);
        yh[(size_t)r * RU4 + i4] = o;
    }
}

// launch 8: HMMA GEMM (mma.sync m16n8k16). Also restores cnt=0 invariant.
// Logical k = m*72+d lives in B (zeros at d>=66); A is unpadded (stride 66).
__global__ void __launch_bounds__(256, 2) k_gemm_mma(
    const __half* __restrict__ x0, const __half* __restrict__ x1a,
    const __half* __restrict__ ya, const __half* __restrict__ x1b,
    const __half* __restrict__ yb, const __half* __restrict__ wt,
    const float* __restrict__ bias, float* __restrict__ out,
    int* __restrict__ cnt) {
    extern __shared__ __half sB[];   // [64][KS]
    int t = threadIdx.x, wid = t >> 5, lane = t & 31;
    int g = lane >> 2, tid4 = lane & 3;

    // restore cnt = 0 for the next call (cnt is dead after k_scan)
    int zi = blockIdx.x * 256 + t;
    if (zi < 2 * N_) cnt[zi] = 0;

    const uint4* wt4 = reinterpret_cast<const uint4*>(wt);
    for (int i = t; i < 3072; i += 256) {
        int r = i / 48, c = i - r * 48;
        *reinterpret_cast<uint4*>(sB + r * KS + c * 8) = wt4[i];
    }
    __syncthreads();

    int p = wid >> 2;               // node within pair
    int b_lo = (wid & 3) * 16 + g;  // batch row (lo); hi = +8
    const __half* xs[5] = {x0, x1a, ya, x1b, yb};

    for (int tile = blockIdx.x; tile < NPAIR; tile += gridDim.x) {
        int n = tile * 2 + p;
        size_t baseL = (size_t)n * RH + (size_t)b_lo * D_ + tid4 * 2;
        size_t baseH = baseL + 8 * D_;

        float acc[8][4];
#pragma unroll
        for (int ng = 0; ng < 8; ng++)
#pragma unroll
            for (int q = 0; q < 4; q++) acc[ng][q] = 0.f;

#pragma unroll
        for (int ks = 0; ks < 23; ks++) {
            const int klo = ks * 16;
            const int khi = klo + 8;
            const int mlo = klo / 72, dlo = klo - mlo * 72;
            const int mhi = khi / 72, dhi = khi - mhi * 72;
            unsigned a0, a1, a2, a3;
            a0 = *reinterpret_cast<const unsigned*>(xs[mlo] + baseL + dlo);
            a1 = *reinterpret_cast<const unsigned*>(xs[mlo] + baseH + dlo);
            if (mhi < 5) {
                a2 = *reinterpret_cast<const unsigned*>(xs[mhi] + baseL + dhi);
                a3 = *reinterpret_cast<const unsigned*>(xs[mhi] + baseH + dhi);
            } else {
                a2 = 0u; a3 = 0u;
            }
#pragma unroll
            for (int ng = 0; ng < 8; ng++) {
                const __half* bp = sB + (ng * 8 + g) * KS + klo + tid4 * 2;
                unsigned b0 = *reinterpret_cast<const unsigned*>(bp);
                unsigned b1 = *reinterpret_cast<const unsigned*>(bp + 8);
                asm volatile(
                    "mma.sync.aligned.m16n8k16.row.col.f32.f16.f16.f32 "
                    "{%0,%1,%2,%3}, {%4,%5,%6,%7}, {%8,%9}, {%0,%1,%2,%3};"
                    : "+f"(acc[ng][0]), "+f"(acc[ng][1]),
                      "+f"(acc[ng][2]), "+f"(acc[ng][3])
                    : "r"(a0), "r"(a1), "r"(a2), "r"(a3), "r"(b0), "r"(b1));
            }
        }

        float* orow_lo = out + (size_t)b_lo * ((size_t)N_ * O_) + (size_t)n * O_;
        float* orow_hi = orow_lo + 8 * ((size_t)N_ * O_);
#pragma unroll
        for (int ng = 0; ng < 8; ng++) {
            int col = ng * 8 + tid4 * 2;
            float2 bv = __ldg(reinterpret_cast<const float2*>(bias + col));
            float2 vlo = make_float2(acc[ng][0] + bv.x, acc[ng][1] + bv.y);
            float2 vhi = make_float2(acc[ng][2] + bv.x, acc[ng][3] + bv.y);
            *reinterpret_cast<float2*>(orow_lo + col) = vlo;
            *reinterpret_cast<float2*>(orow_hi + col) = vhi;
        }
    }
}

// ---------------- launch ----------------
extern "C" void kernel_launch(void* const* d_in, const int* in_sizes, int n_in,
                              void* d_out, int out_size) {
    const float* inputs = (const float*)d_in[0];
    const float* weight = (const float*)d_in[2];
    const float* biases = (const float*)d_in[3];
    const float* vals0  = (const float*)d_in[4];
    const float* vals1  = (const float*)d_in[5];
    const int*   rows0  = (const int*)d_in[6];
    const int*   cols0  = (const int*)d_in[7];
    const int*   rows1  = (const int*)d_in[8];
    const int*   cols1  = (const int*)d_in[9];
    float* out = (float*)d_out;

    __half *x0h, *x1a, *ya, *x1b, *yb, *wt;
    int *cnt, *rp, *cur;
    int2* cvS;
    cudaGetSymbolAddress((void**)&x0h, g_x0h);
    cudaGetSymbolAddress((void**)&x1a, g_x1a);
    cudaGetSymbolAddress((void**)&ya,  g_ya);
    cudaGetSymbolAddress((void**)&x1b, g_x1b);
    cudaGetSymbolAddress((void**)&yb,  g_yb);
    cudaGetSymbolAddress((void**)&wt,  g_wt);
    cudaGetSymbolAddress((void**)&cnt, g_cnt);
    cudaGetSymbolAddress((void**)&rp,  g_rp);
    cudaGetSymbolAddress((void**)&cur, g_cur);
    cudaGetSymbolAddress((void**)&cvS, g_cvS);

    // 1: histogram (cnt zero-on-entry invariant)
    k_hist2<<<(2 * E_ + 255) / 256, 256>>>(rows0, rows1, cnt);
    // 2: scan
    k_scan<<<2, 1024>>>(cnt, rp, cur);
    // 3: fused scatter + transpose + W' build
    k_fuse<<<11250 + (64 * KPAD + 255) / 256, 256>>>(
        rows0, cols0, vals0, rows1, cols1, vals1, cur, cvS,
        inputs, (half2*)x0h, weight, wt);

    int* rp0 = rp;
    int* rp1 = rp + (N_ + 1);
    int2* cvS0 = cvS;
    int2* cvS1 = cvS + E_;

    // 4-7: HMMA SpMM, half-row blocking (stage-1 pair first so x0 stays hot)
    dim3 gs(N_, 2);
    k_spmm_mma<<<gs, 288>>>(rp0, cvS0, (const char*)x0h, (uint4*)x1a);
    k_spmm_mma<<<gs, 288>>>(rp1, cvS1, (const char*)x0h, (uint4*)x1b);
    k_spmm_mma<<<gs, 288>>>(rp0, cvS0, (const char*)x1a, (uint4*)ya);
    k_spmm_mma<<<gs, 288>>>(rp1, cvS1, (const char*)x1b, (uint4*)yb);

    // 8: GEMM (+ cnt re-zero)
    const int smem_gemm = 64 * KS * 2;  // 50176 B
    cudaFuncSetAttribute(k_gemm_mma, cudaFuncAttributeMaxDynamicSharedMemorySize, smem_gemm);
    k_gemm_mma<<<GEMM_GRID, 256, smem_gemm>>>(x0h, x1a, ya, x1b, yb, wt, biases, out, cnt);
}